// round 7
// baseline (speedup 1.0000x reference)
#include <cuda_runtime.h>
#include <cstdint>

// Problem constants
#define HOP     128
#define WINL    512
#define PADW    192
#define NB      32
#define NT      131072
#define NFRM    1024
#define NSTAGE  11

// Tiling: one warp per block, one frame per lane
#define NFB     32
#define BLK_PER_B (NFRM / NFB)             // 32
#define SPAN    ((NFB - 1) * HOP + WINL)   // 4480
#define NROWS   (SPAN / HOP)               // 35
#define SMEMN   (NROWS * (HOP + 1))        // 4515 floats (129-word rows)
#define WINT    260                        // half window table (257 used)
#define SMEM_BYTES ((2 * SMEMN + WINT) * sizeof(float))   // 37160 B -> 6 blocks/SM

#define TWO_PI_OVER_WIN 0.012271846303085129f

__device__ __forceinline__ int pidx(int i) { return i + (i >> 7); }

__device__ __forceinline__ float hannw(int n) {
    return 0.5f - 0.5f * __cosf((float)n * TWO_PI_OVER_WIN);
}

__device__ float norm_at(int p) {
    int f_hi = p >> 7; if (f_hi > NFRM - 1) f_hi = NFRM - 1;
    int f_lo = (p >= 384) ? ((p - 384) >> 7) : 0;
    float s = 0.f;
    for (int f = f_lo; f <= f_hi; ++f) s += hannw(p - (f << 7));
    return s;
}

__global__ void halo_zero_kernel(float* __restrict__ out) {
    int b   = blockIdx.y;
    int blk = blockIdx.x + 1;
    int u   = blk * (NFB * HOP) - PADW + (int)threadIdx.x;
    out[(size_t)b * NT + u] = 0.f;
}

// One cascade step: DST[s] = -a1[s]*SRC[s] - a2[s]*DST[s] + in(s),
// in(0)=X, in(s)=SRC[s-1]. 22 independent FMAs per step.
#define CASCADE(SRC, DST, X)                                          \
    DST##0  = fmaf(na2_0,  DST##0,  fmaf(na1_0,  SRC##0,  (X)));      \
    DST##1  = fmaf(na2_1,  DST##1,  fmaf(na1_1,  SRC##1,  SRC##0));   \
    DST##2  = fmaf(na2_2,  DST##2,  fmaf(na1_2,  SRC##2,  SRC##1));   \
    DST##3  = fmaf(na2_3,  DST##3,  fmaf(na1_3,  SRC##3,  SRC##2));   \
    DST##4  = fmaf(na2_4,  DST##4,  fmaf(na1_4,  SRC##4,  SRC##3));   \
    DST##5  = fmaf(na2_5,  DST##5,  fmaf(na1_5,  SRC##5,  SRC##4));   \
    DST##6  = fmaf(na2_6,  DST##6,  fmaf(na1_6,  SRC##6,  SRC##5));   \
    DST##7  = fmaf(na2_7,  DST##7,  fmaf(na1_7,  SRC##7,  SRC##6));   \
    DST##8  = fmaf(na2_8,  DST##8,  fmaf(na1_8,  SRC##8,  SRC##7));   \
    DST##9  = fmaf(na2_9,  DST##9,  fmaf(na1_9,  SRC##9,  SRC##8));   \
    DST##10 = fmaf(na2_10, DST##10, fmaf(na1_10, SRC##10, SRC##9));

// 8 steps, pure store (chunk 0 first-writes), ascending window wb[O+k].
#define G8_ST(O, XB) {                                                \
    float _w0 = wb[(O)+0], _w1 = wb[(O)+1],                            \
          _w2 = wb[(O)+2], _w3 = wb[(O)+3];                            \
    CASCADE(pa, pb, g*(XB)[0]); ob[(O)+0] = pb10 * _w0;                \
    CASCADE(pb, pa, g*(XB)[1]); ob[(O)+1] = pa10 * _w1;                \
    float _w4 = wb[(O)+4], _w5 = wb[(O)+5],                            \
          _w6 = wb[(O)+6], _w7 = wb[(O)+7];                            \
    CASCADE(pa, pb, g*(XB)[2]); ob[(O)+2] = pb10 * _w2;                \
    CASCADE(pb, pa, g*(XB)[3]); ob[(O)+3] = pa10 * _w3;                \
    CASCADE(pa, pb, g*(XB)[4]); ob[(O)+4] = pb10 * _w4;                \
    CASCADE(pb, pa, g*(XB)[5]); ob[(O)+5] = pa10 * _w5;                \
    CASCADE(pa, pb, g*(XB)[6]); ob[(O)+6] = pb10 * _w6;                \
    CASCADE(pb, pa, g*(XB)[7]); ob[(O)+7] = pa10 * _w7; }

// 8 steps, accumulate, ascending window wb[O+k] (chunk 1).
#define G8_ACP(O, XB) {                                               \
    float _o0 = ob[(O)+0], _o1 = ob[(O)+1],                            \
          _o2 = ob[(O)+2], _o3 = ob[(O)+3];                            \
    float _w0 = wb[(O)+0], _w1 = wb[(O)+1],                            \
          _w2 = wb[(O)+2], _w3 = wb[(O)+3];                            \
    CASCADE(pa, pb, g*(XB)[0]); ob[(O)+0] = fmaf(pb10, _w0, _o0);      \
    CASCADE(pb, pa, g*(XB)[1]); ob[(O)+1] = fmaf(pa10, _w1, _o1);      \
    float _o4 = ob[(O)+4], _o5 = ob[(O)+5],                            \
          _o6 = ob[(O)+6], _o7 = ob[(O)+7];                            \
    float _w4 = wb[(O)+4], _w5 = wb[(O)+5],                            \
          _w6 = wb[(O)+6], _w7 = wb[(O)+7];                            \
    CASCADE(pa, pb, g*(XB)[2]); ob[(O)+2] = fmaf(pb10, _w2, _o2);      \
    CASCADE(pb, pa, g*(XB)[3]); ob[(O)+3] = fmaf(pa10, _w3, _o3);      \
    CASCADE(pa, pb, g*(XB)[4]); ob[(O)+4] = fmaf(pb10, _w4, _o4);      \
    CASCADE(pb, pa, g*(XB)[5]); ob[(O)+5] = fmaf(pa10, _w5, _o5);      \
    CASCADE(pa, pb, g*(XB)[6]); ob[(O)+6] = fmaf(pb10, _w6, _o6);      \
    CASCADE(pb, pa, g*(XB)[7]); ob[(O)+7] = fmaf(pa10, _w7, _o7); }

// 8 steps, accumulate, DESCENDING window wd[15-O-k] (chunks 2,3 use the
// mirrored half-table: win[j] == win[512-j]).
#define G8_ACM(O, XB) {                                               \
    float _o0 = ob[(O)+0], _o1 = ob[(O)+1],                            \
          _o2 = ob[(O)+2], _o3 = ob[(O)+3];                            \
    float _w0 = wd[15-(O)-0], _w1 = wd[15-(O)-1],                      \
          _w2 = wd[15-(O)-2], _w3 = wd[15-(O)-3];                      \
    CASCADE(pa, pb, g*(XB)[0]); ob[(O)+0] = fmaf(pb10, _w0, _o0);      \
    CASCADE(pb, pa, g*(XB)[1]); ob[(O)+1] = fmaf(pa10, _w1, _o1);      \
    float _o4 = ob[(O)+4], _o5 = ob[(O)+5],                            \
          _o6 = ob[(O)+6], _o7 = ob[(O)+7];                            \
    float _w4 = wd[15-(O)-4], _w5 = wd[15-(O)-5],                      \
          _w6 = wd[15-(O)-6], _w7 = wd[15-(O)-7];                      \
    CASCADE(pa, pb, g*(XB)[2]); ob[(O)+2] = fmaf(pb10, _w2, _o2);      \
    CASCADE(pb, pa, g*(XB)[3]); ob[(O)+3] = fmaf(pa10, _w3, _o3);      \
    CASCADE(pa, pb, g*(XB)[4]); ob[(O)+4] = fmaf(pb10, _w4, _o4);      \
    CASCADE(pb, pa, g*(XB)[5]); ob[(O)+5] = fmaf(pa10, _w5, _o5);      \
    CASCADE(pa, pb, g*(XB)[6]); ob[(O)+6] = fmaf(pb10, _w6, _o6);      \
    CASCADE(pb, pa, g*(XB)[7]); ob[(O)+7] = fmaf(pa10, _w7, _o7); }

#define PFETCH16(DST, P, OFF)                                          \
    _Pragma("unroll")                                                  \
    for (int _k = 0; _k < 16; ++_k) (DST)[_k] = (P)[(OFF) + _k];

__global__ __launch_bounds__(NFB) void synth_kernel(const float* __restrict__ ex,
                                                    const float* __restrict__ gain,
                                                    const float* __restrict__ bq,
                                                    float* __restrict__ out) {
    extern __shared__ float sm[];
    float* in_s  = sm;                 // SMEMN floats, 129-stride padded
    float* out_s = sm + SMEMN;         // SMEMN floats
    float* win_s = sm + 2 * SMEMN;     // 257 floats (hann half-table)

    const int b   = blockIdx.y;
    const int blk = blockIdx.x;
    const int F0  = blk * NFB;
    const int S0  = F0 * HOP;
    const int tid = (int)threadIdx.x;
    const int kbase = tid * (HOP + 1);

    // ---- Phase A: coalesced staging of the input span into padded smem.
    // 1120 quads, 35 rounds of 32 lanes; quads never straddle pad rows.
    {
        const float* exb = ex + (size_t)b * NT + (S0 - PADW);
        #pragma unroll 1
        for (int it = 0; it < NROWS; ++it) {
            int e   = it * 128 + tid * 4;
            int pos = S0 - PADW + e;
            float4 v = make_float4(0.f, 0.f, 0.f, 0.f);
            if ((unsigned)pos <= (unsigned)(NT - 4))
                v = *(const float4*)(exb + e);
            int o = e + (e >> 7);
            in_s[o] = v.x; in_s[o+1] = v.y; in_s[o+2] = v.z; in_s[o+3] = v.w;
        }
        for (int i = tid; i <= 256; i += NFB) win_s[i] = hannw(i);
        for (int i = NFB * HOP + tid; i < SPAN; i += NFB) out_s[pidx(i)] = 0.f;
    }

    // ---- Per-frame coefficients (negated for FMA form)
    const int f = F0 + tid;
    const float g = gain[b * NFRM + f];
    const float* bp = bq + (size_t)(b * NFRM + f) * (NSTAGE * 3);
    const float na1_0  = -bp[1],  na2_0  = -bp[2];
    const float na1_1  = -bp[4],  na2_1  = -bp[5];
    const float na1_2  = -bp[7],  na2_2  = -bp[8];
    const float na1_3  = -bp[10], na2_3  = -bp[11];
    const float na1_4  = -bp[13], na2_4  = -bp[14];
    const float na1_5  = -bp[16], na2_5  = -bp[17];
    const float na1_6  = -bp[19], na2_6  = -bp[20];
    const float na1_7  = -bp[22], na2_7  = -bp[23];
    const float na1_8  = -bp[25], na2_8  = -bp[26];
    const float na1_9  = -bp[28], na2_9  = -bp[29];
    const float na1_10 = -bp[31], na2_10 = -bp[32];

    float pa0 = 0.f, pa1 = 0.f, pa2 = 0.f, pa3 = 0.f, pa4 = 0.f, pa5 = 0.f,
          pa6 = 0.f, pa7 = 0.f, pa8 = 0.f, pa9 = 0.f, pa10 = 0.f;
    float pb0 = 0.f, pb1 = 0.f, pb2 = 0.f, pb3 = 0.f, pb4 = 0.f, pb5 = 0.f,
          pb6 = 0.f, pb7 = 0.f, pb8 = 0.f, pb9 = 0.f, pb10 = 0.f;

    __syncwarp();   // staging is cooperative; cascade reads other lanes' rows

    float xc[16], xn[16];

    // ---- Prologue: t = 0..9 (fill filter pipeline), preload chunk-0 ss0
    {
        const float* ib0 = in_s + kbase;     // t>>7 == 0 here
        float xp[10];
        #pragma unroll
        for (int k = 0; k < 10; ++k) xp[k] = ib0[k];
        PFETCH16(xc, ib0, 10);               // inputs t = 10..25
        CASCADE(pa, pb, g * xp[0]); CASCADE(pb, pa, g * xp[1]);
        CASCADE(pa, pb, g * xp[2]); CASCADE(pb, pa, g * xp[3]);
        CASCADE(pa, pb, g * xp[4]); CASCADE(pb, pa, g * xp[5]);
        CASCADE(pa, pb, g * xp[6]); CASCADE(pb, pa, g * xp[7]);
        CASCADE(pa, pb, g * xp[8]); CASCADE(pb, pa, g * xp[9]);
    }

    // Per-chunk input base: ip = in_s + kbase + 129*c + 10; ip[e] is input
    // t = 128c+10+e while (t>>7)==c (e < 118). The >>7 bump (+1 word) hits
    // only e>=118, handled in the peeled superstep-6 prefetch. For chunk 3,
    // e>=118 means t>=512: zero-input drain instead.

    // ---- Chunk 0: outputs j in [0,128), pure stores.
    {
        float* ob = out_s + kbase;
        const float* wb = win_s;
        const float* ip = in_s + kbase + 10;
        #pragma unroll 1
        for (int ss = 0; ss < 6; ss += 2) {
            PFETCH16(xn, ip, 16);
            G8_ST(0, (xc+0)) G8_ST(8, (xc+8))
            ob += 16; wb += 16; ip += 16;
            PFETCH16(xc, ip, 16);
            G8_ST(0, (xn+0)) G8_ST(8, (xn+8))
            ob += 16; wb += 16; ip += 16;
        }
        #pragma unroll
        for (int k = 0; k < 6; ++k)  xn[k] = ip[16 + k];
        #pragma unroll
        for (int k = 6; k < 16; ++k) xn[k] = ip[17 + k];
        G8_ST(0, (xc+0)) G8_ST(8, (xc+8))
        ob += 16; wb += 16; ip += 16;
        PFETCH16(xc, ip, 17);                 // next chunk ss0 (base + 129)
        G8_ST(0, (xn+0)) G8_ST(8, (xn+8))
        __syncwarp();
    }

    // ---- Chunk 1: outputs j in [128,256), accumulate, ascending window.
    {
        float* ob = out_s + kbase + 128 + 1;
        const float* wb = win_s + 128;
        const float* ip = in_s + kbase + 129 + 10;
        #pragma unroll 1
        for (int ss = 0; ss < 6; ss += 2) {
            PFETCH16(xn, ip, 16);
            G8_ACP(0, (xc+0)) G8_ACP(8, (xc+8))
            ob += 16; wb += 16; ip += 16;
            PFETCH16(xc, ip, 16);
            G8_ACP(0, (xn+0)) G8_ACP(8, (xn+8))
            ob += 16; wb += 16; ip += 16;
        }
        #pragma unroll
        for (int k = 0; k < 6; ++k)  xn[k] = ip[16 + k];
        #pragma unroll
        for (int k = 6; k < 16; ++k) xn[k] = ip[17 + k];
        G8_ACP(0, (xc+0)) G8_ACP(8, (xc+8))
        ob += 16; wb += 16; ip += 16;
        PFETCH16(xc, ip, 17);
        G8_ACP(0, (xn+0)) G8_ACP(8, (xn+8))
        __syncwarp();
    }

    // ---- Chunk 2: outputs j in [256,384), accumulate, mirrored window
    // idx = 512-j = 256-e  ->  wd starts at win_s+241, steps -16.
    {
        float* ob = out_s + kbase + 256 + 2;
        const float* wd = win_s + 241;
        const float* ip = in_s + kbase + 258 + 10;
        #pragma unroll 1
        for (int ss = 0; ss < 6; ss += 2) {
            PFETCH16(xn, ip, 16);
            G8_ACM(0, (xc+0)) G8_ACM(8, (xc+8))
            ob += 16; wd -= 16; ip += 16;
            PFETCH16(xc, ip, 16);
            G8_ACM(0, (xn+0)) G8_ACM(8, (xn+8))
            ob += 16; wd -= 16; ip += 16;
        }
        #pragma unroll
        for (int k = 0; k < 6; ++k)  xn[k] = ip[16 + k];
        #pragma unroll
        for (int k = 6; k < 16; ++k) xn[k] = ip[17 + k];
        G8_ACM(0, (xc+0)) G8_ACM(8, (xc+8))
        ob += 16; wd -= 16; ip += 16;
        PFETCH16(xc, ip, 17);
        G8_ACM(0, (xn+0)) G8_ACM(8, (xn+8))
        __syncwarp();
    }

    // ---- Chunk 3: outputs j in [384,512), accumulate, mirrored window
    // idx = 128-e -> wd starts at win_s+113. Inputs end at e=118 (t=512):
    // the last 10 steps drain with x = 0.
    {
        float* ob = out_s + kbase + 384 + 3;
        const float* wd = win_s + 113;
        const float* ip = in_s + kbase + 387 + 10;
        #pragma unroll 1
        for (int ss = 0; ss < 6; ss += 2) {
            PFETCH16(xn, ip, 16);
            G8_ACM(0, (xc+0)) G8_ACM(8, (xc+8))
            ob += 16; wd -= 16; ip += 16;
            PFETCH16(xc, ip, 16);
            G8_ACM(0, (xn+0)) G8_ACM(8, (xn+8))
            ob += 16; wd -= 16; ip += 16;
        }
        #pragma unroll
        for (int k = 0; k < 6; ++k)  xn[k] = ip[16 + k];   // t = 506..511
        #pragma unroll
        for (int k = 6; k < 16; ++k) xn[k] = 0.f;          // t >= 512: drain
        G8_ACM(0, (xc+0)) G8_ACM(8, (xc+8))
        ob += 16; wd -= 16; ip += 16;
        G8_ACM(0, (xn+0)) G8_ACM(8, (xn+8))
        __syncwarp();
    }

    // ---- Phase C: write out. Interior norm == 2.0; halos via atomics into
    // pre-zeroed columns.
    const int lo = (F0 == 0) ? 0 : 384;
    const int hi = (F0 + NFB >= NFRM) ? SPAN : NFB * HOP;
    for (int i = tid; i < SPAN; i += NFB) {
        int p = S0 + i;
        int u = p - PADW;
        if (u < 0 || u >= NT) continue;
        float w = out_s[pidx(i)];
        if (p >= 384 && p < NFRM * HOP) w *= 0.5f;
        else                            w /= norm_at(p);
        float* dst = out + (size_t)b * NT + u;
        if (i >= lo && i < hi) *dst = w;
        else                   atomicAdd(dst, w);
    }
}

extern "C" void kernel_launch(void* const* d_in, const int* in_sizes, int n_in,
                              void* d_out, int out_size) {
    const float* ex   = (const float*)d_in[0];   // (32, 131072) f32
    const float* gain = (const float*)d_in[1];   // (32, 1024)   f32
    const float* bq   = (const float*)d_in[2];   // (32, 1024, 11, 3) f32
    float* out = (float*)d_out;                  // (32, 131072) f32

    cudaFuncSetAttribute(synth_kernel, cudaFuncAttributeMaxDynamicSharedMemorySize,
                         (int)SMEM_BYTES);

    halo_zero_kernel<<<dim3(BLK_PER_B - 1, NB), 384>>>(out);
    synth_kernel<<<dim3(BLK_PER_B, NB), NFB, SMEM_BYTES>>>(ex, gain, bq, out);
}

// round 8
// speedup vs baseline: 1.5363x; 1.5363x over previous
#include <cuda_runtime.h>
#include <cstdint>

// Problem constants
#define HOP     128
#define WINL    512
#define PADW    192
#define NB      32
#define NT      131072
#define NFRM    1024
#define NSTAGE  11

// Tiling: one warp per block, one frame per lane (R5 skeleton: single wave)
#define NFB     32
#define BLK_PER_B (NFRM / NFB)             // 32
#define SPAN    ((NFB - 1) * HOP + WINL)   // 4480
#define NROWS   (SPAN / HOP)               // 35
#define SMEMN   (NROWS * (HOP + 1))        // 4515 floats (129-word rows)
#define SMEM_BYTES ((SMEMN + WINL) * sizeof(float))   // ~20.1 KB -> all 1024 warps resident

#define TWO_PI_OVER_WIN 0.012271846303085129f

typedef unsigned long long u64;

// ---- packed f32x2 primitives (Blackwell FFMA2 path) ----
#define PK2(D, LO, HI) \
    asm("mov.b64 %0, {%1, %2};" : "=l"(D) : "r"(__float_as_uint(LO)), "r"(__float_as_uint(HI)))
#define UP2(FL, FH, S) { unsigned _ua, _ub;                                        \
    asm("mov.b64 {%0, %1}, %2;" : "=r"(_ua), "=r"(_ub) : "l"(S));                  \
    (FL) = __uint_as_float(_ua); (FH) = __uint_as_float(_ub); }
#define LO2(F, S) { unsigned _ua, _ub;                                             \
    asm("mov.b64 {%0, %1}, %2;" : "=r"(_ua), "=r"(_ub) : "l"(S));                  \
    (F) = __uint_as_float(_ua); (void)_ub; }
#define FMA2(D, A, B, C) \
    asm("fma.rn.f32x2 %0, %1, %2, %3;" : "=l"(D) : "l"(A), "l"(B), "l"(C))

__device__ __forceinline__ int pidx(int i) { return i + (i >> 7); }

__device__ __forceinline__ float hannw(int n) {
    return 0.5f - 0.5f * __cosf((float)n * TWO_PI_OVER_WIN);
}

__device__ float norm_at(int p) {
    int f_hi = p >> 7; if (f_hi > NFRM - 1) f_hi = NFRM - 1;
    int f_lo = (p >= 384) ? ((p - 384) >> 7) : 0;
    float s = 0.f;
    for (int f = f_lo; f <= f_hi; ++f) s += hannw(p - (f << 7));
    return s;
}

__global__ void halo_zero_kernel(float* __restrict__ out) {
    int b   = blockIdx.y;
    int blk = blockIdx.x + 1;
    int u   = blk * (NFB * HOP) - PADW + (int)threadIdx.x;
    out[(size_t)b * NT + u] = 0.f;
}

// One cascade step over 12 stages (stage 11 is a dummy with zero coeffs) as
// 6 lane-pairs. Lane math identical to scalar fmaf chain:
//   inner_k = fma2(NA1_k, S_k, F_k)   F_k = (in(2k), in(2k+1)) = (y[2k-1], y[2k]) prev-step
//   D_k     = fma2(NA2_k, D_k, inner_k)     (D_k holds state from 2 steps ago)
// Output tap: y10 = lo(D5).
#define CASCADE2(SRC, DST, X) {                                       \
    float _l0,_h0,_l1,_h1,_l2,_h2,_l3,_h3,_l4,_h4,_l5,_h5;            \
    UP2(_l0,_h0, SRC##0); UP2(_l1,_h1, SRC##1);                        \
    UP2(_l2,_h2, SRC##2); UP2(_l3,_h3, SRC##3);                        \
    UP2(_l4,_h4, SRC##4); UP2(_l5,_h5, SRC##5); (void)_h5;             \
    u64 _F0,_F1,_F2,_F3,_F4,_F5;                                       \
    PK2(_F0, (X), _l0);  PK2(_F1, _h0, _l1);  PK2(_F2, _h1, _l2);      \
    PK2(_F3, _h2, _l3);  PK2(_F4, _h3, _l4);  PK2(_F5, _h4, _l5);      \
    u64 _I0,_I1,_I2,_I3,_I4,_I5;                                       \
    FMA2(_I0, NA1_0, SRC##0, _F0);                                     \
    FMA2(_I1, NA1_1, SRC##1, _F1);                                     \
    FMA2(_I2, NA1_2, SRC##2, _F2);                                     \
    FMA2(_I3, NA1_3, SRC##3, _F3);                                     \
    FMA2(_I4, NA1_4, SRC##4, _F4);                                     \
    FMA2(_I5, NA1_5, SRC##5, _F5);                                     \
    FMA2(DST##0, NA2_0, DST##0, _I0);                                  \
    FMA2(DST##1, NA2_1, DST##1, _I1);                                  \
    FMA2(DST##2, NA2_2, DST##2, _I2);                                  \
    FMA2(DST##3, NA2_3, DST##3, _I3);                                  \
    FMA2(DST##4, NA2_4, DST##4, _I4);                                  \
    FMA2(DST##5, NA2_5, DST##5, _I5); }

// 8-step group, accumulating OLA (ob/wb carry immediate offsets).
#define G8_ACC(JJ, i0, i1, i2, i3, i4, i5, i6, i7) {                  \
    float _o0 = ob[(JJ)+0], _o1 = ob[(JJ)+1],                          \
          _o2 = ob[(JJ)+2], _o3 = ob[(JJ)+3];                          \
    float _w0 = wb[(JJ)+0], _w1 = wb[(JJ)+1],                          \
          _w2 = wb[(JJ)+2], _w3 = wb[(JJ)+3];                          \
    float _y;                                                          \
    CASCADE2(qa, qb, g*(i0)); LO2(_y, qb5); ob[(JJ)+0] = fmaf(_y, _w0, _o0); \
    CASCADE2(qb, qa, g*(i1)); LO2(_y, qa5); ob[(JJ)+1] = fmaf(_y, _w1, _o1); \
    float _o4 = ob[(JJ)+4], _o5 = ob[(JJ)+5],                          \
          _o6 = ob[(JJ)+6], _o7 = ob[(JJ)+7];                          \
    float _w4 = wb[(JJ)+4], _w5 = wb[(JJ)+5],                          \
          _w6 = wb[(JJ)+6], _w7 = wb[(JJ)+7];                          \
    CASCADE2(qa, qb, g*(i2)); LO2(_y, qb5); ob[(JJ)+2] = fmaf(_y, _w2, _o2); \
    CASCADE2(qb, qa, g*(i3)); LO2(_y, qa5); ob[(JJ)+3] = fmaf(_y, _w3, _o3); \
    CASCADE2(qa, qb, g*(i4)); LO2(_y, qb5); ob[(JJ)+4] = fmaf(_y, _w4, _o4); \
    CASCADE2(qb, qa, g*(i5)); LO2(_y, qa5); ob[(JJ)+5] = fmaf(_y, _w5, _o5); \
    CASCADE2(qa, qb, g*(i6)); LO2(_y, qb5); ob[(JJ)+6] = fmaf(_y, _w6, _o6); \
    CASCADE2(qb, qa, g*(i7)); LO2(_y, qa5); ob[(JJ)+7] = fmaf(_y, _w7, _o7); }

// 8-step group, first write of each OLA slot (chunk 0): pure store.
#define G8_STORE(JJ, i0, i1, i2, i3, i4, i5, i6, i7) {                \
    float _w0 = wb[(JJ)+0], _w1 = wb[(JJ)+1],                          \
          _w2 = wb[(JJ)+2], _w3 = wb[(JJ)+3];                          \
    float _y;                                                          \
    CASCADE2(qa, qb, g*(i0)); LO2(_y, qb5); ob[(JJ)+0] = _y * _w0;     \
    CASCADE2(qb, qa, g*(i1)); LO2(_y, qa5); ob[(JJ)+1] = _y * _w1;     \
    float _w4 = wb[(JJ)+4], _w5 = wb[(JJ)+5],                          \
          _w6 = wb[(JJ)+6], _w7 = wb[(JJ)+7];                          \
    CASCADE2(qa, qb, g*(i2)); LO2(_y, qb5); ob[(JJ)+2] = _y * _w2;     \
    CASCADE2(qb, qa, g*(i3)); LO2(_y, qa5); ob[(JJ)+3] = _y * _w3;     \
    CASCADE2(qa, qb, g*(i4)); LO2(_y, qb5); ob[(JJ)+4] = _y * _w4;     \
    CASCADE2(qb, qa, g*(i5)); LO2(_y, qa5); ob[(JJ)+5] = _y * _w5;     \
    CASCADE2(qa, qb, g*(i6)); LO2(_y, qb5); ob[(JJ)+6] = _y * _w6;     \
    CASCADE2(qb, qa, g*(i7)); LO2(_y, qa5); ob[(JJ)+7] = _y * _w7; }

// 16-step superstep (carry x0,x1 + quads c0..c3).
#define SS16_ACC(JJ)                                                   \
    G8_ACC((JJ),     x0,   x1,   c0.x, c0.y, c0.z, c0.w, c1.x, c1.y)   \
    G8_ACC((JJ) + 8, c1.z, c1.w, c2.x, c2.y, c2.z, c2.w, c3.x, c3.y)

#define SS16_STORE(JJ)                                                 \
    G8_STORE((JJ),     x0,   x1,   c0.x, c0.y, c0.z, c0.w, c1.x, c1.y) \
    G8_STORE((JJ) + 8, c1.z, c1.w, c2.x, c2.y, c2.z, c2.w, c3.x, c3.y)

// Guarded 16B-aligned quad load of input elements t = 4k..4k+3.
__device__ __forceinline__ float4 ld4g(const float* __restrict__ xp, int pos0, int k) {
    int pos = pos0 + 4 * k;
    if ((unsigned)pos <= (unsigned)(NT - 4))
        return *(const float4*)(xp + 4 * k);
    return make_float4(0.f, 0.f, 0.f, 0.f);
}

__global__ __launch_bounds__(NFB) void synth_kernel(const float* __restrict__ ex,
                                                    const float* __restrict__ gain,
                                                    const float* __restrict__ bq,
                                                    float* __restrict__ out) {
    extern __shared__ float sm[];
    float* out_s = sm;                // SMEMN floats
    float* win_s = sm + SMEMN;        // WINL floats

    const int b   = blockIdx.y;
    const int blk = blockIdx.x;
    const int F0  = blk * NFB;
    const int S0  = F0 * HOP;
    const int tid = (int)threadIdx.x;
    const int kbase = tid * (HOP + 1);

    // Per-thread input stream (element t=0; may be out of range at edges)
    const int   pos0 = S0 + tid * HOP - PADW;
    const float* xp  = ex + (size_t)b * NT + pos0;

    // Early loads: prologue quads q0..q2, superstep-0 quads c0..c3
    float4 q0 = ld4g(xp, pos0, 0);
    float4 q1 = ld4g(xp, pos0, 1);
    float4 q2 = ld4g(xp, pos0, 2);
    float4 c0 = ld4g(xp, pos0, 3);
    float4 c1 = ld4g(xp, pos0, 4);
    float4 c2 = ld4g(xp, pos0, 5);
    float4 c3 = ld4g(xp, pos0, 6);

    // ---- Phase A: zero out_s tail rows; window table
    for (int i = NFB * HOP + tid; i < SPAN; i += NFB) out_s[pidx(i)] = 0.f;
    for (int i = tid; i < WINL; i += NFB) win_s[i] = hannw(i);

    // ---- Per-frame coefficients: negate and pack into stage-pair f32x2
    const int f = F0 + tid;
    const float g = gain[b * NFRM + f];
    const float* bp = bq + (size_t)(b * NFRM + f) * (NSTAGE * 3);
    u64 NA1_0, NA1_1, NA1_2, NA1_3, NA1_4, NA1_5;
    u64 NA2_0, NA2_1, NA2_2, NA2_3, NA2_4, NA2_5;
    PK2(NA1_0, -bp[1],  -bp[4]);   PK2(NA2_0, -bp[2],  -bp[5]);
    PK2(NA1_1, -bp[7],  -bp[10]);  PK2(NA2_1, -bp[8],  -bp[11]);
    PK2(NA1_2, -bp[13], -bp[16]);  PK2(NA2_2, -bp[14], -bp[17]);
    PK2(NA1_3, -bp[19], -bp[22]);  PK2(NA2_3, -bp[20], -bp[23]);
    PK2(NA1_4, -bp[25], -bp[28]);  PK2(NA2_4, -bp[26], -bp[29]);
    PK2(NA1_5, -bp[31], 0.0f);     PK2(NA2_5, -bp[32], 0.0f);   // stage 11 = dummy

    // Packed ping-pong state: pairs (y0,y1)(y2,y3)...(y10,y11)
    u64 qa0 = 0, qa1 = 0, qa2 = 0, qa3 = 0, qa4 = 0, qa5 = 0;
    u64 qb0 = 0, qb1 = 0, qb2 = 0, qb3 = 0, qb4 = 0, qb5 = 0;

    __syncwarp();   // out_s tail + win_s visible warp-wide

    // ---- Prologue: t = 0..9 fill the filter pipeline (no output)
    CASCADE2(qa, qb, g * q0.x); CASCADE2(qb, qa, g * q0.y);
    CASCADE2(qa, qb, g * q0.z); CASCADE2(qb, qa, g * q0.w);
    CASCADE2(qa, qb, g * q1.x); CASCADE2(qb, qa, g * q1.y);
    CASCADE2(qa, qb, g * q1.z); CASCADE2(qb, qa, g * q1.w);
    CASCADE2(qa, qb, g * q2.x); CASCADE2(qb, qa, g * q2.y);
    float x0 = q2.z, x1 = q2.w;           // carry: t = 10, 11

    // ---- Chunk 0: t in [10,138). Pure stores; prefetch next superstep's
    // quads (16 steps ahead).
    {
        float* ob = out_s + kbase;
        const float* wb = win_s;
        #pragma unroll 2
        for (int ss = 0; ss < 8; ++ss) {
            const int kq = 7 + 4 * ss;
            float4 n0 = ld4g(xp, pos0, kq);
            float4 n1 = ld4g(xp, pos0, kq + 1);
            float4 n2 = ld4g(xp, pos0, kq + 2);
            float4 n3 = ld4g(xp, pos0, kq + 3);
            SS16_STORE(ss * 16);
            x0 = c3.z; x1 = c3.w;
            c0 = n0; c1 = n1; c2 = n2; c3 = n3;
        }
        __syncwarp();
    }

    // ---- Chunks 1,2: accumulating OLA.
    #pragma unroll 1
    for (int c = 1; c <= 2; ++c) {
        float* ob = out_s + kbase + 128 * c + c;    // (j>>7)==c folded in
        const float* wb = win_s + 128 * c;
        const int kqb = 7 + 32 * c;
        #pragma unroll 2
        for (int ss = 0; ss < 8; ++ss) {
            const int kq = kqb + 4 * ss;
            float4 n0 = ld4g(xp, pos0, kq);
            float4 n1 = ld4g(xp, pos0, kq + 1);
            float4 n2 = ld4g(xp, pos0, kq + 2);
            float4 n3 = ld4g(xp, pos0, kq + 3);
            SS16_ACC(ss * 16);
            x0 = c3.z; x1 = c3.w;
            c0 = n0; c1 = n1; c2 = n2; c3 = n3;
        }
        __syncwarp();
    }

    // ---- Chunk 3: t in [394,522). Supersteps 0..5 uniform; 6 peeled
    // (fetch only quad 127); 7 peeled with zero-input drain for t >= 512.
    {
        float* ob = out_s + kbase + 384 + 3;
        const float* wb = win_s + 384;
        #pragma unroll 2
        for (int ss = 0; ss < 6; ++ss) {
            const int kq = 103 + 4 * ss;
            float4 n0 = ld4g(xp, pos0, kq);
            float4 n1 = ld4g(xp, pos0, kq + 1);
            float4 n2 = ld4g(xp, pos0, kq + 2);
            float4 n3 = ld4g(xp, pos0, kq + 3);
            SS16_ACC(ss * 16);
            x0 = c3.z; x1 = c3.w;
            c0 = n0; c1 = n1; c2 = n2; c3 = n3;
        }
        float4 qq = ld4g(xp, pos0, 127);
        SS16_ACC(96);
        x0 = c3.z; x1 = c3.w;                        // t = 506, 507
        G8_ACC(112, x0, x1, qq.x, qq.y, qq.z, qq.w, 0.f, 0.f);
        G8_ACC(120, 0.f, 0.f, 0.f, 0.f, 0.f, 0.f, 0.f, 0.f);
        __syncwarp();
    }

    // ---- Phase C: write out. Interior norm == 2.0; halos via atomics into
    // pre-zeroed columns.
    const int lo = (F0 == 0) ? 0 : 384;
    const int hi = (F0 + NFB >= NFRM) ? SPAN : NFB * HOP;
    for (int i = tid; i < SPAN; i += NFB) {
        int p = S0 + i;
        int u = p - PADW;
        if (u < 0 || u >= NT) continue;
        float w = out_s[pidx(i)];
        if (p >= 384 && p < NFRM * HOP) w *= 0.5f;
        else                            w /= norm_at(p);
        float* dst = out + (size_t)b * NT + u;
        if (i >= lo && i < hi) *dst = w;
        else                   atomicAdd(dst, w);
    }
}

extern "C" void kernel_launch(void* const* d_in, const int* in_sizes, int n_in,
                              void* d_out, int out_size) {
    const float* ex   = (const float*)d_in[0];   // (32, 131072) f32
    const float* gain = (const float*)d_in[1];   // (32, 1024)   f32
    const float* bq   = (const float*)d_in[2];   // (32, 1024, 11, 3) f32
    float* out = (float*)d_out;                  // (32, 131072) f32

    cudaFuncSetAttribute(synth_kernel, cudaFuncAttributeMaxDynamicSharedMemorySize,
                         (int)SMEM_BYTES);

    halo_zero_kernel<<<dim3(BLK_PER_B - 1, NB), 384>>>(out);
    synth_kernel<<<dim3(BLK_PER_B, NB), NFB, SMEM_BYTES>>>(ex, gain, bq, out);
}